// round 16
// baseline (speedup 1.0000x reference)
#include <cuda_runtime.h>
#include <cstdint>

#define B_ 64
#define T_ 1024
#define I_ 256
#define H_ 512

typedef unsigned long long u64;

// ---------------- packed f32x2 helpers (sm_103a) ----------------
__device__ __forceinline__ u64 pack2(float lo, float hi) {
    u64 r; asm("mov.b64 %0, {%1, %2};" : "=l"(r) : "f"(lo), "f"(hi)); return r;
}
__device__ __forceinline__ u64 fma2(u64 a, u64 b, u64 c) {
    u64 d; asm("fma.rn.f32x2 %0, %1, %2, %3;" : "=l"(d) : "l"(a), "l"(b), "l"(c)); return d;
}
__device__ __forceinline__ u64 add2(u64 a, u64 b) {
    u64 d; asm("add.rn.f32x2 %0, %1, %2;" : "=l"(d) : "l"(a), "l"(b)); return d;
}
__device__ __forceinline__ float2 unpack2(u64 v) {
    float2 r; asm("mov.b64 {%0, %1}, %2;" : "=f"(r.x), "=f"(r.y) : "l"(v)); return r;
}

// ---------------- static device scratch ----------------
// Projections stored transposed: [t][j][b]  -> index (t*H_ + j)*B_ + b
__device__ float g_xz[(size_t)T_ * H_ * B_];
__device__ float g_xr[(size_t)T_ * H_ * B_];
__device__ float g_xh[(size_t)T_ * H_ * B_];
// Hidden state double buffer + r*h exchange, layout [b][j]
__device__ float g_h[2][B_ * H_];
__device__ float g_rh[B_ * H_];
// Per-(batch-group, super-chunk) monotone counters; 128B apart.
// A super-chunk = 4 col-CTAs = 128 h-columns. Reset by proj kernel each launch.
struct __align__(128) Cnt { unsigned c; unsigned pad[31]; };
__device__ Cnt g_hc[32];    // h-next produced:  [bg*4 + sc]
__device__ Cnt g_rhc[32];   // rh produced:      [bg*4 + sc]

// warp-uniform acquire-poll (all lanes; coalesces to one request per poll)
__device__ __forceinline__ void poll_(const unsigned* p, unsigned th) {
    unsigned v;
    do {
        asm volatile("ld.acquire.gpu.u32 %0, [%1];" : "=r"(v) : "l"(p) : "memory");
    } while (v < th);
}
__device__ __forceinline__ void bump_(unsigned* p) {
    asm volatile("red.release.gpu.add.u32 [%0], %1;" :: "l"(p), "r"(1u) : "memory");
}

// =================================================================================
// Projection GEMM (proven) + counter reset (replay safety)
// =================================================================================
__global__ __launch_bounds__(256) void gru_proj_kernel(
    const float* __restrict__ xs,
    const float* __restrict__ Wz, const float* __restrict__ Wr, const float* __restrict__ Wh,
    const float* __restrict__ bz, const float* __restrict__ br, const float* __restrict__ bh)
{
    __shared__ float As[8 * 132];
    __shared__ float Bs[8 * 132];

    if (blockIdx.x == 0 && blockIdx.y == 0 && blockIdx.z == 0 && threadIdx.x < 32) {
        g_hc[threadIdx.x].c  = 0u;
        g_rhc[threadIdx.x].c = 0u;
    }

    const int g = blockIdx.z;
    const float* W    = (g == 0) ? Wz : (g == 1) ? Wr : Wh;
    const float* bias = (g == 0) ? bz : (g == 1) ? br : bh;
    float*       out  = (g == 0) ? g_xz : (g == 1) ? g_xr : g_xh;

    const int m0 = blockIdx.x * 128;
    const int n0 = blockIdx.y * 128;
    const int tid = (int)threadIdx.x;

    const int tx = tid & 15;
    const int ty = tid >> 4;

    const int arow = tid >> 1, aseg = tid & 1;
    const int brow = tid >> 5, bcol4 = (tid & 31) * 4;

    u64 acc2[8][4];
#pragma unroll
    for (int i = 0; i < 8; ++i)
#pragma unroll
        for (int j = 0; j < 4; ++j) acc2[i][j] = 0ull;

    for (int k0 = 0; k0 < I_; k0 += 8) {
        float4 av = *(const float4*)&xs[(size_t)(m0 + arow) * I_ + k0 + aseg * 4];
        float4 bv = *(const float4*)&W[(size_t)(k0 + brow) * H_ + n0 + bcol4];
        __syncthreads();
        As[(aseg * 4 + 0) * 132 + arow] = av.x;
        As[(aseg * 4 + 1) * 132 + arow] = av.y;
        As[(aseg * 4 + 2) * 132 + arow] = av.z;
        As[(aseg * 4 + 3) * 132 + arow] = av.w;
        *(float4*)&Bs[brow * 132 + bcol4] = bv;
        __syncthreads();
#pragma unroll
        for (int kk = 0; kk < 8; ++kk) {
            float a[8];
            float4 a0 = *(const float4*)&As[kk * 132 + ty * 8];
            float4 a1 = *(const float4*)&As[kk * 132 + ty * 8 + 4];
            ulonglong2 bq0 = *(const ulonglong2*)&Bs[kk * 132 + tx * 8];
            ulonglong2 bq1 = *(const ulonglong2*)&Bs[kk * 132 + tx * 8 + 4];
            a[0]=a0.x; a[1]=a0.y; a[2]=a0.z; a[3]=a0.w;
            a[4]=a1.x; a[5]=a1.y; a[6]=a1.z; a[7]=a1.w;
            u64 bp[4] = { bq0.x, bq0.y, bq1.x, bq1.y };
#pragma unroll
            for (int i = 0; i < 8; ++i) {
                u64 ap = pack2(a[i], a[i]);
#pragma unroll
                for (int j = 0; j < 4; ++j) acc2[i][j] = fma2(ap, bp[j], acc2[i][j]);
            }
        }
    }

#pragma unroll
    for (int j = 0; j < 4; ++j) {
        const int n = n0 + tx * 8 + 2 * j;
        const float bi0 = bias[n], bi1 = bias[n + 1];
#pragma unroll
        for (int i = 0; i < 8; ++i) {
            const int m = m0 + ty * 8 + i;
            const int t = m & (T_ - 1);
            const int b = m >> 10;
            float2 v = unpack2(acc2[i][j]);
            out[(size_t)(t * H_ + n) * B_ + b]     = v.x + bi0;
            out[(size_t)(t * H_ + n + 1) * B_ + b] = v.y + bi1;
        }
    }
}

// =================================================================================
// Persistent recurrence: 128 CTAs = 8 batch-groups x 16 col-groups, 256 thr, 1/SM.
// CTA owns 8 batches x 32 h-columns. Exchanges are per-super-chunk pipelined:
// poll counter -> LDG 4KB chunk -> STS -> sync -> FMA, own super-chunk first,
// next chunk's poll+LDG overlapping current chunk's FMA.
// =================================================================================
#define NB_CTA 8
#define NC_CTA 32
#define HS_S 520               // h_s[bl*520 + k]; LDS.64 bank = (8b + 2lane)&31
#define WS_S 100               // per-plane: w[k2*100 + c]
#define SMEM_FLOATS (NB_CTA * HS_S + 2 * (H_/2) * WS_S)
#define SMEM_BYTES  (SMEM_FLOATS * 4)

__device__ __forceinline__ float sigmoidf_(float x) {
    return 1.0f / (1.0f + expf(-x));
}

#define RSTAGE64(arr, N, M, lane)                                            \
    {                                                                        \
        const bool hi_ = ((lane) & (M)) != 0;                                \
        _Pragma("unroll")                                                    \
        for (int i_ = 0; i_ < (N); ++i_) {                                   \
            u64 send_ = hi_ ? arr[i_] : arr[i_ + (N)];                       \
            u64 recv_ = __shfl_xor_sync(0xffffffffu, send_, (M));            \
            u64 keep_ = hi_ ? arr[i_ + (N)] : arr[i_];                       \
            arr[i_] = add2(keep_, recv_);                                    \
        }                                                                    \
    }

// Two k2-iterations (one 128-k super-chunk) of the proven 16-acc dot body.
#define DOT16_2IT(accv, cbase, it0)                                          \
    _Pragma("unroll")                                                        \
    for (int ii = 0; ii < 2; ++ii) {                                         \
        const int k2 = lane + (((it0) + ii) << 5);                           \
        ulonglong2 wq0 = *(const ulonglong2*)&w_ev[k2 * WS_S + (cbase)];     \
        ulonglong2 wq1 = *(const ulonglong2*)&w_od[k2 * WS_S + (cbase)];     \
        float2 hv2[8];                                                       \
        _Pragma("unroll")                                                    \
        for (int b = 0; b < 8; ++b)                                          \
            hv2[b] = *(const float2*)&h_s[b * HS_S + 2 * k2];                \
        _Pragma("unroll")                                                    \
        for (int b = 0; b < 8; ++b) {                                        \
            u64 hb0 = pack2(hv2[b].x, hv2[b].x);                             \
            u64 hb1 = pack2(hv2[b].y, hv2[b].y);                             \
            accv[b]     = fma2(wq0.x, hb0, accv[b]);                         \
            accv[b]     = fma2(wq1.x, hb1, accv[b]);                         \
            accv[8 + b] = fma2(wq0.y, hb0, accv[8 + b]);                     \
            accv[8 + b] = fma2(wq1.y, hb1, accv[8 + b]);                     \
        }                                                                    \
    }

// Proven tree: lane l -> col pair (cp=(l>>4)&1), batch (l>>1)&7, parity l&1.
#define DOT16_TREE(accv)                                                     \
    RSTAGE64(accv, 8, 16, lane)                                              \
    RSTAGE64(accv, 4,  8, lane)                                              \
    RSTAGE64(accv, 2,  4, lane)                                              \
    RSTAGE64(accv, 1,  2, lane)                                              \
    accv[0] = add2(accv[0], __shfl_xor_sync(0xffffffffu, accv[0], 1));

__global__ __launch_bounds__(256, 1) void gru_rec_kernel(
    const float* __restrict__ Wz, const float* __restrict__ Wr, const float* __restrict__ Wh,
    float* __restrict__ out)
{
    extern __shared__ float smem[];
    float* h_s  = smem;                        // NB_CTA * 520
    float* w_ev = h_s + NB_CTA * HS_S;         // 256 * 100 (even k)
    float* w_od = w_ev + (H_/2) * WS_S;        // 256 * 100 (odd k)

    const int tid  = (int)threadIdx.x;
    const int w    = tid >> 5;
    const int lane = tid & 31;
    const int bg   = (int)blockIdx.x >> 4;     // batch group 0..7
    const int cg   = (int)blockIdx.x & 15;     // col group 0..15
    const int col0 = cg * NC_CTA;
    const int bc0  = bg * NB_CTA;
    const int sc0  = cg >> 2;                  // own super-chunk 0..3

    // ---- one-time: 96 weight columns (32 z | 32 r | 32 cand), split by k parity --
    for (int i = tid; i < H_ * 96; i += 256) {
        const int k = i / 96, c = i % 96;
        const float* W = (c < 32) ? Wz : (c < 64) ? Wr : Wh;
        float* dst = (k & 1) ? w_od : w_ev;
        dst[(k >> 1) * WS_S + c] = W[(size_t)(I_ + k) * H_ + col0 + (c & 31)];
    }
    __syncthreads();   // w planes ready

    // ---- chunk staging geometry: thread -> (batch bl, float4 kq) within chunk ----
    const int bl = tid >> 5;                   // batch 0..7 (one warp per batch row)
    const int kq = tid & 31;                   // float4 index within 128-k chunk

    // ---- lane mappings (identical for all three dot phases) ----
    const int cpA  = (lane >> 4) & 1;
    const int bA   = (lane >> 1) & 7;
    const int parA = lane & 1;
    const int jA   = 4 * w + 2 * cpA + parA;   // local col 0..31

    // ---- software-pipelined x-gate operands ----
    const size_t x0 = (size_t)(col0 + jA) * B_ + bc0 + bA;
    const size_t xstep = (size_t)H_ * B_;
    float xr_c = __ldcg(&g_xr[x0]);
    float xz_c = __ldcg(&g_xz[x0]);
    float xh_c = __ldcg(&g_xh[x0]);

#pragma unroll 1
    for (int t = 0; t < T_; ++t) {
        const unsigned thr_h  = 4u * (unsigned)t;         // h chunks of step t
        const unsigned thr_rh = 4u * (unsigned)(t + 1);   // rh chunks of step t

        // ==== phase A: pipelined h chunks; fused r + z dots per chunk ====
        u64 accA[16], accZ[16];
#pragma unroll
        for (int i = 0; i < 16; ++i) { accA[i] = 0ull; accZ[i] = 0ull; }

        if (t == 0) {
            // h0 = 0: fill whole h_s once, no polls
#pragma unroll
            for (int u = 0; u < 4; ++u) {
                const int i = tid + u * 256;
                const int b2 = i >> 7, k4 = (i & 127) << 2;
                *(float4*)&h_s[b2 * HS_S + k4] = make_float4(0.f, 0.f, 0.f, 0.f);
            }
            __syncthreads();
#pragma unroll
            for (int d = 0; d < 4; ++d) {
                const int s = (sc0 + d) & 3;
                DOT16_2IT(accA, 32 + 4 * w, 2 * s)
                DOT16_2IT(accZ, 4 * w, 2 * s)
            }
        } else {
            const float4* hsrc = (const float4*)&g_h[t & 1][(size_t)bc0 * H_];
            poll_(&g_hc[bg * 4 + sc0].c, thr_h);
            float4 v = __ldcg(hsrc + bl * 128 + sc0 * 32 + kq);
#pragma unroll 1
            for (int d = 0; d < 4; ++d) {
                const int s = (sc0 + d) & 3;
                *(float4*)&h_s[bl * HS_S + s * 128 + kq * 4] = v;
                __syncthreads();
                if (d < 3) {
                    const int sn = (sc0 + d + 1) & 3;
                    poll_(&g_hc[bg * 4 + sn].c, thr_h);
                    v = __ldcg(hsrc + bl * 128 + sn * 32 + kq);
                }
                DOT16_2IT(accA, 32 + 4 * w, 2 * s)
                DOT16_2IT(accZ, 4 * w, 2 * s)
            }
        }
        DOT16_TREE(accA)
        DOT16_TREE(accZ)

        float z_reg, hold_reg;
        {
            float2 dr = unpack2(accA[0]);
            float2 dz = unpack2(accZ[0]);
            const float rdot = parA ? dr.y : dr.x;
            const float zdot = parA ? dz.y : dz.x;
            const float r = sigmoidf_(xr_c + rdot);
            z_reg    = sigmoidf_(xz_c + zdot);
            hold_reg = h_s[bA * HS_S + col0 + jA];
            __stcg(&g_rh[(size_t)(bc0 + bA) * H_ + col0 + jA], r * hold_reg);
        }
        __syncthreads();           // all rh stores done; all A-FMA reads done
        if (tid == 0) bump_(&g_rhc[bg * 4 + sc0].c);

        // ==== phase B: pipelined rh chunks; cand dots ====
        u64 accB[16];
#pragma unroll
        for (int i = 0; i < 16; ++i) accB[i] = 0ull;
        {
            const float4* rsrc = (const float4*)&g_rh[(size_t)bc0 * H_];
            poll_(&g_rhc[bg * 4 + sc0].c, thr_rh);
            float4 v = __ldcg(rsrc + bl * 128 + sc0 * 32 + kq);
#pragma unroll 1
            for (int d = 0; d < 4; ++d) {
                const int s = (sc0 + d) & 3;
                *(float4*)&h_s[bl * HS_S + s * 128 + kq * 4] = v;
                __syncthreads();
                if (d < 3) {
                    const int sn = (sc0 + d + 1) & 3;
                    poll_(&g_rhc[bg * 4 + sn].c, thr_rh);
                    v = __ldcg(rsrc + bl * 128 + sn * 32 + kq);
                }
                DOT16_2IT(accB, 64 + 4 * w, 2 * s)
            }
        }
        DOT16_TREE(accB)

        {
            float2 pr = unpack2(accB[0]);
            const float cand = parA ? pr.y : pr.x;
            const float ht = tanhf(xh_c + cand);
            const float hn = fmaf(z_reg, ht - hold_reg, hold_reg);
            const int gb = bc0 + bA;
            out[(size_t)gb * T_ * H_ + (size_t)t * H_ + col0 + jA] = hn;
            __stcg(&g_h[(t + 1) & 1][(size_t)gb * H_ + col0 + jA], hn);
            if (t == T_ - 1)
                out[(size_t)B_ * T_ * H_ + (size_t)gb * H_ + col0 + jA] = hn;
        }
        // prefetch next step's gate operands (hides DRAM latency under exchange)
        if (t + 1 < T_) {
            const size_t xn = x0 + (size_t)(t + 1) * xstep;
            xr_c = __ldcg(&g_xr[xn]);
            xz_c = __ldcg(&g_xz[xn]);
            xh_c = __ldcg(&g_xh[xn]);
        }
        __syncthreads();           // all h-next stores + B-FMA reads done
        if (tid == 0) bump_(&g_hc[bg * 4 + sc0].c);
    }
}

// =================================================================================
extern "C" void kernel_launch(void* const* d_in, const int* in_sizes, int n_in,
                              void* d_out, int out_size) {
    const float* xs = (const float*)d_in[0];
    const float* Wz = (const float*)d_in[1];
    const float* bz = (const float*)d_in[2];
    const float* Wr = (const float*)d_in[3];
    const float* br = (const float*)d_in[4];
    const float* Wh = (const float*)d_in[5];
    const float* bh = (const float*)d_in[6];
    float* out = (float*)d_out;

    cudaFuncSetAttribute(gru_rec_kernel,
                         cudaFuncAttributeMaxDynamicSharedMemorySize, SMEM_BYTES);

    dim3 pg(T_ * B_ / 128, H_ / 128, 3);
    gru_proj_kernel<<<pg, 256>>>(xs, Wz, Wr, Wh, bz, br, bh);

    gru_rec_kernel<<<128, 256, SMEM_BYTES>>>(Wz, Wr, Wh, out);
}

// round 17
// speedup vs baseline: 1.1645x; 1.1645x over previous
#include <cuda_runtime.h>
#include <cstdint>

#define B_ 64
#define T_ 1024
#define I_ 256
#define H_ 512

typedef unsigned long long u64;

// ---------------- packed f32x2 helpers (sm_103a) ----------------
__device__ __forceinline__ u64 pack2(float lo, float hi) {
    u64 r; asm("mov.b64 %0, {%1, %2};" : "=l"(r) : "f"(lo), "f"(hi)); return r;
}
__device__ __forceinline__ u64 fma2(u64 a, u64 b, u64 c) {
    u64 d; asm("fma.rn.f32x2 %0, %1, %2, %3;" : "=l"(d) : "l"(a), "l"(b), "l"(c)); return d;
}
__device__ __forceinline__ u64 add2(u64 a, u64 b) {
    u64 d; asm("add.rn.f32x2 %0, %1, %2;" : "=l"(d) : "l"(a), "l"(b)); return d;
}
__device__ __forceinline__ float2 unpack2(u64 v) {
    float2 r; asm("mov.b64 {%0, %1}, %2;" : "=f"(r.x), "=f"(r.y) : "l"(v)); return r;
}

// ---------------- static device scratch ----------------
// Projections stored transposed: [t][j][b]  -> index (t*H_ + j)*B_ + b
__device__ float g_xz[(size_t)T_ * H_ * B_];
__device__ float g_xr[(size_t)T_ * H_ * B_];
__device__ float g_xh[(size_t)T_ * H_ * B_];
// Hidden state double buffer + r*h exchange, layout [b][j]
__device__ float g_h[2][B_ * H_];
__device__ float g_rh[B_ * H_];
// Per-batch-group barrier: 8 slots, 128B apart; count MONOTONE within a launch
// (reset by proj kernel each replay). Waiters poll count >= 16*instance.
struct __align__(128) BarSlot { unsigned count; unsigned pad[31]; };
__device__ BarSlot g_bar[8];

// ---------------- split barrier (16 CTAs/group), monotone count ----------------
__device__ __forceinline__ void group_arrive_(int bg) {
    __syncthreads();
    if (threadIdx.x == 0) {
        asm volatile("red.release.gpu.add.u32 [%0], %1;"
                     :: "l"(&g_bar[bg].count), "r"(1u) : "memory");
    }
}
__device__ __forceinline__ void group_wait_(int bg, unsigned thresh) {
    if (threadIdx.x == 0) {
        unsigned v;
        do {
            asm volatile("ld.acquire.gpu.u32 %0, [%1];"
                         : "=r"(v) : "l"(&g_bar[bg].count) : "memory");
        } while (v < thresh);
    }
    __syncthreads();
}

// =================================================================================
// Projection GEMM (proven) + barrier-slot reset (replay safety)
// =================================================================================
__global__ __launch_bounds__(256) void gru_proj_kernel(
    const float* __restrict__ xs,
    const float* __restrict__ Wz, const float* __restrict__ Wr, const float* __restrict__ Wh,
    const float* __restrict__ bz, const float* __restrict__ br, const float* __restrict__ bh)
{
    __shared__ float As[8 * 132];
    __shared__ float Bs[8 * 132];

    if (blockIdx.x == 0 && blockIdx.y == 0 && blockIdx.z == 0 && threadIdx.x < 8) {
        g_bar[threadIdx.x].count = 0u;
    }

    const int g = blockIdx.z;
    const float* W    = (g == 0) ? Wz : (g == 1) ? Wr : Wh;
    const float* bias = (g == 0) ? bz : (g == 1) ? br : bh;
    float*       out  = (g == 0) ? g_xz : (g == 1) ? g_xr : g_xh;

    const int m0 = blockIdx.x * 128;
    const int n0 = blockIdx.y * 128;
    const int tid = (int)threadIdx.x;

    const int tx = tid & 15;
    const int ty = tid >> 4;

    const int arow = tid >> 1, aseg = tid & 1;
    const int brow = tid >> 5, bcol4 = (tid & 31) * 4;

    u64 acc2[8][4];
#pragma unroll
    for (int i = 0; i < 8; ++i)
#pragma unroll
        for (int j = 0; j < 4; ++j) acc2[i][j] = 0ull;

    for (int k0 = 0; k0 < I_; k0 += 8) {
        float4 av = *(const float4*)&xs[(size_t)(m0 + arow) * I_ + k0 + aseg * 4];
        float4 bv = *(const float4*)&W[(size_t)(k0 + brow) * H_ + n0 + bcol4];
        __syncthreads();
        As[(aseg * 4 + 0) * 132 + arow] = av.x;
        As[(aseg * 4 + 1) * 132 + arow] = av.y;
        As[(aseg * 4 + 2) * 132 + arow] = av.z;
        As[(aseg * 4 + 3) * 132 + arow] = av.w;
        *(float4*)&Bs[brow * 132 + bcol4] = bv;
        __syncthreads();
#pragma unroll
        for (int kk = 0; kk < 8; ++kk) {
            float a[8];
            float4 a0 = *(const float4*)&As[kk * 132 + ty * 8];
            float4 a1 = *(const float4*)&As[kk * 132 + ty * 8 + 4];
            ulonglong2 bq0 = *(const ulonglong2*)&Bs[kk * 132 + tx * 8];
            ulonglong2 bq1 = *(const ulonglong2*)&Bs[kk * 132 + tx * 8 + 4];
            a[0]=a0.x; a[1]=a0.y; a[2]=a0.z; a[3]=a0.w;
            a[4]=a1.x; a[5]=a1.y; a[6]=a1.z; a[7]=a1.w;
            u64 bp[4] = { bq0.x, bq0.y, bq1.x, bq1.y };
#pragma unroll
            for (int i = 0; i < 8; ++i) {
                u64 ap = pack2(a[i], a[i]);
#pragma unroll
                for (int j = 0; j < 4; ++j) acc2[i][j] = fma2(ap, bp[j], acc2[i][j]);
            }
        }
    }

#pragma unroll
    for (int j = 0; j < 4; ++j) {
        const int n = n0 + tx * 8 + 2 * j;
        const float bi0 = bias[n], bi1 = bias[n + 1];
#pragma unroll
        for (int i = 0; i < 8; ++i) {
            const int m = m0 + ty * 8 + i;
            const int t = m & (T_ - 1);
            const int b = m >> 10;
            float2 v = unpack2(acc2[i][j]);
            out[(size_t)(t * H_ + n) * B_ + b]     = v.x + bi0;
            out[(size_t)(t * H_ + n + 1) * B_ + b] = v.y + bi1;
        }
    }
}

// =================================================================================
// Persistent recurrence: 128 CTAs = 8 batch-groups x 16 col-groups, 256 thr, 1/SM.
// CTA owns 8 batches x 32 h-columns. Phase A1: r dots -> rh -> ARRIVE.
// Phase A2 (overlaps barrier wait): z dots. WAIT -> stage rh -> phase B.
// z and hold stay in registers (same lane mapping across phases).
// =================================================================================
#define NB_CTA 8
#define NC_CTA 32
#define HS_S 520               // h_s[bl*520 + k]; LDS.64 bank = (8b + 2lane)&31
#define WS_S 100               // per-plane: w[k2*100 + c]
#define SMEM_FLOATS (NB_CTA * HS_S + 2 * (H_/2) * WS_S)
#define SMEM_BYTES  (SMEM_FLOATS * 4)

__device__ __forceinline__ float sigmoidf_(float x) {
    return 1.0f / (1.0f + expf(-x));
}

#define RSTAGE64(arr, N, M, lane)                                            \
    {                                                                        \
        const bool hi_ = ((lane) & (M)) != 0;                                \
        _Pragma("unroll")                                                    \
        for (int i_ = 0; i_ < (N); ++i_) {                                   \
            u64 send_ = hi_ ? arr[i_] : arr[i_ + (N)];                       \
            u64 recv_ = __shfl_xor_sync(0xffffffffu, send_, (M));            \
            u64 keep_ = hi_ ? arr[i_ + (N)] : arr[i_];                       \
            arr[i_] = add2(keep_, recv_);                                    \
        }                                                                    \
    }

// 16-acc dot block, paired-k (even/odd weight planes). After tree: lane l
// holds pair for col 2cp+par (cp=(l>>4)&1, par=l&1), batch (l>>1)&7.
#define DOT16(accv, cbase)                                                   \
    _Pragma("unroll")                                                        \
    for (int i = 0; i < 16; ++i) accv[i] = 0ull;                             \
    _Pragma("unroll 4")                                                      \
    for (int it = 0; it < 8; ++it) {                                         \
        const int k2 = lane + (it << 5);                                     \
        ulonglong2 wq0 = *(const ulonglong2*)&w_ev[k2 * WS_S + (cbase)];     \
        ulonglong2 wq1 = *(const ulonglong2*)&w_od[k2 * WS_S + (cbase)];     \
        float2 hv2[8];                                                       \
        _Pragma("unroll")                                                    \
        for (int b = 0; b < 8; ++b)                                          \
            hv2[b] = *(const float2*)&h_s[b * HS_S + 2 * k2];                \
        _Pragma("unroll")                                                    \
        for (int b = 0; b < 8; ++b) {                                        \
            u64 hb0 = pack2(hv2[b].x, hv2[b].x);                             \
            u64 hb1 = pack2(hv2[b].y, hv2[b].y);                             \
            accv[b]     = fma2(wq0.x, hb0, accv[b]);                         \
            accv[b]     = fma2(wq1.x, hb1, accv[b]);                         \
            accv[8 + b] = fma2(wq0.y, hb0, accv[8 + b]);                     \
            accv[8 + b] = fma2(wq1.y, hb1, accv[8 + b]);                     \
        }                                                                    \
    }                                                                        \
    RSTAGE64(accv, 8, 16, lane)                                              \
    RSTAGE64(accv, 4,  8, lane)                                              \
    RSTAGE64(accv, 2,  4, lane)                                              \
    RSTAGE64(accv, 1,  2, lane)                                              \
    accv[0] = add2(accv[0], __shfl_xor_sync(0xffffffffu, accv[0], 1));

// Stage 8-batch slice: 1024 float4, 4 per thread, LDG-batched.
__device__ __forceinline__ void stage_h_(float* h_s, const float4* __restrict__ src, int tid) {
    float4 v[4];
#pragma unroll
    for (int u = 0; u < 4; ++u)
        v[u] = __ldcg(src + tid + u * 256);
#pragma unroll
    for (int u = 0; u < 4; ++u) {
        const int i = tid + u * 256;
        const int bl = i >> 7;
        const int k4 = (i & 127) << 2;
        *(float4*)&h_s[bl * HS_S + k4] = v[u];
    }
}

__global__ __launch_bounds__(256, 1) void gru_rec_kernel(
    const float* __restrict__ Wz, const float* __restrict__ Wr, const float* __restrict__ Wh,
    float* __restrict__ out)
{
    extern __shared__ float smem[];
    float* h_s  = smem;                        // NB_CTA * 520
    float* w_ev = h_s + NB_CTA * HS_S;         // 256 * 100 (even k)
    float* w_od = w_ev + (H_/2) * WS_S;        // 256 * 100 (odd k)

    const int tid  = (int)threadIdx.x;
    const int w    = tid >> 5;
    const int lane = tid & 31;
    const int bg   = (int)blockIdx.x >> 4;     // batch group 0..7
    const int cg   = (int)blockIdx.x & 15;     // col group 0..15
    const int col0 = cg * NC_CTA;
    const int bc0  = bg * NB_CTA;

    // ---- one-time: 96 weight columns (32 z | 32 r | 32 cand), split by k parity --
    for (int i = tid; i < H_ * 96; i += 256) {
        const int k = i / 96, c = i % 96;
        const float* W = (c < 32) ? Wz : (c < 64) ? Wr : Wh;
        float* dst = (k & 1) ? w_od : w_ev;
        dst[(k >> 1) * WS_S + c] = W[(size_t)(I_ + k) * H_ + col0 + (c & 31)];
    }

    // ---- lane mappings for the 16-acc tree (all three phases) ----
    const int cpA  = (lane >> 4) & 1;
    const int bA   = (lane >> 1) & 7;
    const int parA = lane & 1;
    const int jA   = 4 * w + 2 * cpA + parA;   // local col 0..31

    // ---- software-pipelined x-gate operands ----
    const size_t x0 = (size_t)(col0 + jA) * B_ + bc0 + bA;
    const size_t xstep = (size_t)H_ * B_;
    float xr_c = __ldcg(&g_xr[x0]);
    float xz_c = __ldcg(&g_xz[x0]);
    float xh_c = __ldcg(&g_xh[x0]);

#pragma unroll 1
    for (int t = 0; t < T_; ++t) {
        // ---- stage h slice (layout [local b][k]); t==0: h = 0 ----
        __syncthreads();   // h_s free (covers w staging on iter 0)
        if (t == 0) {
#pragma unroll
            for (int u = 0; u < 4; ++u) {
                const int i = tid + u * 256;
                const int bl = i >> 7, k4 = (i & 127) << 2;
                *(float4*)&h_s[bl * HS_S + k4] = make_float4(0.f, 0.f, 0.f, 0.f);
            }
        } else {
            stage_h_(h_s, (const float4*)&g_h[t & 1][(size_t)bc0 * H_], tid);
        }
        __syncthreads();

        // ---- phase A1: r dots (col slots 32..63) -> rh -> ARRIVE ----
        u64 accA[16];
        DOT16(accA, 32 + 4 * w)
        float hold_reg;
        {
            float2 dp = unpack2(accA[0]);
            const float dot = parA ? dp.y : dp.x;
            const float r   = sigmoidf_(xr_c + dot);
            hold_reg = h_s[bA * HS_S + col0 + jA];
            __stcg(&g_rh[(size_t)(bc0 + bA) * H_ + col0 + jA], r * hold_reg);
        }
        group_arrive_(bg);

        // ---- phase A2 (overlaps barrier wait): z dots (slots 0..31) ----
        u64 accZ[16];
        DOT16(accZ, 4 * w)
        float z_reg;
        {
            float2 dp = unpack2(accZ[0]);
            const float dot = parA ? dp.y : dp.x;
            z_reg = sigmoidf_(xz_c + dot);
        }
        group_wait_(bg, 16u * (2u * (unsigned)t + 1u));

        // ---- stage r*h slice (overwrites h_s; hold/z live in registers) ----
        stage_h_(h_s, (const float4*)&g_rh[(size_t)bc0 * H_], tid);
        __syncthreads();

        // ---- phase B: candidate dots (slots 64..95) ----
        u64 accB[16];
        DOT16(accB, 64 + 4 * w)
        {
            float2 pr = unpack2(accB[0]);
            const float cand = parA ? pr.y : pr.x;
            const float ht = tanhf(xh_c + cand);
            const float hn = fmaf(z_reg, ht - hold_reg, hold_reg);
            const int gb = bc0 + bA;
            out[(size_t)gb * T_ * H_ + (size_t)t * H_ + col0 + jA] = hn;
            __stcg(&g_h[(t + 1) & 1][(size_t)gb * H_ + col0 + jA], hn);
            if (t == T_ - 1)
                out[(size_t)B_ * T_ * H_ + (size_t)gb * H_ + col0 + jA] = hn;
        }
        // prefetch next step's gate operands under the barrier-2 shadow
        if (t + 1 < T_) {
            const size_t xn = x0 + (size_t)(t + 1) * xstep;
            xr_c = __ldcg(&g_xr[xn]);
            xz_c = __ldcg(&g_xz[xn]);
            xh_c = __ldcg(&g_xh[xn]);
        }
        group_arrive_(bg);
        group_wait_(bg, 16u * (2u * (unsigned)t + 2u));
    }
}

// =================================================================================
extern "C" void kernel_launch(void* const* d_in, const int* in_sizes, int n_in,
                              void* d_out, int out_size) {
    const float* xs = (const float*)d_in[0];
    const float* Wz = (const float*)d_in[1];
    const float* bz = (const float*)d_in[2];
    const float* Wr = (const float*)d_in[3];
    const float* br = (const float*)d_in[4];
    const float* Wh = (const float*)d_in[5];
    const float* bh = (const float*)d_in[6];
    float* out = (float*)d_out;

    cudaFuncSetAttribute(gru_rec_kernel,
                         cudaFuncAttributeMaxDynamicSharedMemorySize, SMEM_BYTES);

    dim3 pg(T_ * B_ / 128, H_ / 128, 3);
    gru_proj_kernel<<<pg, 256>>>(xs, Wz, Wr, Wh, bz, br, bh);

    gru_rec_kernel<<<128, 256, SMEM_BYTES>>>(Wz, Wr, Wh, out);
}